// round 9
// baseline (speedup 1.0000x reference)
#include <cuda_runtime.h>
#include <math.h>

// Problem constants (fixed-shape benchmark)
#define NN 50000
#define HH 16
#define RR 32
#define CC 8
#define EE 1600000

// Scratch (device globals; no allocation allowed)
__device__ float g_cnt[NN * RR];   // per-(dst,rel) edge counts, [dst][r] layout, 6.4 MB
__device__ int   g_deg[NN];        // per-dst degree (row-sum of cnt)
__device__ int   g_off[NN];        // exclusive offsets; post-scatter: off[n] = start[n+1]
__device__ int2  g_ep[EE];         // per-edge record: (src | r<<16, bitcast inv)
__device__ float g_x[NN * HH];     // layer-1 node features

// ---------------------------------------------------------------- (0) zero cnt
__global__ void k_zero() {
    int i = blockIdx.x * blockDim.x + threadIdx.x;
    if (i < NN * RR / 4) ((float4*)g_cnt)[i] = make_float4(0.f, 0.f, 0.f, 0.f);
}

// ---------------------------------------------------------------- (1) count per (dst, rel)
__global__ void k_count(const int* __restrict__ ei, const int* __restrict__ et) {
    int e = blockIdx.x * blockDim.x + threadIdx.x;
    if (e >= EE) return;
    int dst = __ldg(ei + EE + e);
    int r   = __ldg(et + e);
    atomicAdd(&g_cnt[dst * RR + r], 1.0f);
}

// ---------------------------------------------------------------- (2) deg[n] = sum_r cnt[n][r]
__global__ void k_scanA() {
    int n = blockIdx.x * blockDim.x + threadIdx.x;
    if (n >= NN) return;
    const float4* p = (const float4*)(g_cnt + n * RR);
    float s = 0.f;
    #pragma unroll
    for (int i = 0; i < RR / 4; i++) {
        float4 v = __ldg(&p[i]);
        s += v.x + v.y + v.z + v.w;
    }
    g_deg[n] = (int)(s + 0.5f);
}

// ---------------------------------------------------------------- (3) exclusive scan deg -> off (1 block)
__global__ void k_scanB() {
    __shared__ int ssum[1024];
    int t = threadIdx.x;
    const int CH = (NN + 1023) / 1024;   // 49
    int base = t * CH;
    int tot = 0;
    for (int i = 0; i < CH; i++) {
        int idx = base + i;
        if (idx < NN) tot += g_deg[idx];
    }
    ssum[t] = tot;
    __syncthreads();
    for (int d = 1; d < 1024; d <<= 1) {
        int v = 0;
        if (t >= d) v = ssum[t - d];
        __syncthreads();
        if (t >= d) ssum[t] += v;
        __syncthreads();
    }
    int run = (t > 0) ? ssum[t - 1] : 0;
    for (int i = 0; i < CH; i++) {
        int idx = base + i;
        if (idx < NN) { g_off[idx] = run; run += g_deg[idx]; }
    }
}

// ---------------------------------------------------------------- (4) scatter packed edge records
// g_off doubles as cursor; afterwards g_off[n] = start of node n+1.
__global__ void k_scatter(const int* __restrict__ ei, const int* __restrict__ et) {
    int e = blockIdx.x * blockDim.x + threadIdx.x;
    if (e >= EE) return;
    int src = __ldg(ei + e);
    int dst = __ldg(ei + EE + e);
    int r   = __ldg(et + e);
    float inv = __frcp_rn(g_cnt[dst * RR + r]);   // cnt >= 1 for existing edges
    int pos = atomicAdd(&g_off[dst], 1);
    g_ep[pos] = make_int2(src | (r << 16), __float_as_int(inv));
}

// ---------------------------------------------------------------- (5) layer 1, CSR, 16 lanes/node, fused act
__global__ void __launch_bounds__(256)
k_layer1(const float* __restrict__ w1, const float* __restrict__ root1,
         const float* __restrict__ b1) {
    int tid = blockIdx.x * 256 + threadIdx.x;
    int n = tid >> 4;
    int f = tid & 15;
    if (n >= NN) return;
    int start = (n > 0) ? __ldg(&g_off[n - 1]) : 0;
    int m     = __ldg(&g_deg[n]);
    float acc = 0.f;
    int k = 0;
    for (; k + 4 <= m; k += 4) {
        int2 e0 = __ldg(&g_ep[start + k]);
        int2 e1 = __ldg(&g_ep[start + k + 1]);
        int2 e2 = __ldg(&g_ep[start + k + 2]);
        int2 e3 = __ldg(&g_ep[start + k + 3]);
        float w0 = __ldcs(&w1[(((e0.x >> 16) * NN + (e0.x & 0xFFFF)) << 4) + f]);
        float w1v= __ldcs(&w1[(((e1.x >> 16) * NN + (e1.x & 0xFFFF)) << 4) + f]);
        float w2v= __ldcs(&w1[(((e2.x >> 16) * NN + (e2.x & 0xFFFF)) << 4) + f]);
        float w3v= __ldcs(&w1[(((e3.x >> 16) * NN + (e3.x & 0xFFFF)) << 4) + f]);
        acc += w0 * __int_as_float(e0.y);
        acc += w1v * __int_as_float(e1.y);
        acc += w2v * __int_as_float(e2.y);
        acc += w3v * __int_as_float(e3.y);
    }
    for (; k < m; k++) {
        int2 ep = __ldg(&g_ep[start + k]);
        float w = __ldcs(&w1[(((ep.x >> 16) * NN + (ep.x & 0xFFFF)) << 4) + f]);
        acc += w * __int_as_float(ep.y);
    }
    float v = acc + __ldg(&root1[n * 16 + f]) + __ldg(&b1[f]);
    g_x[n * 16 + f] = fmaxf(v, 0.f);
}

// ---------------------------------------------------------------- (6) layer 2, CSR, 8 lanes/node, fused epilogue
// out[n,c] = log_softmax( sum_e inv_e * (x[src_e] @ w2[r_e])[c] + x[n]@root2 + b2 )
__global__ void __launch_bounds__(256)
k_layer2(const float* __restrict__ w2, const float* __restrict__ root2,
         const float* __restrict__ b2, float* __restrict__ out) {
    __shared__ float sw[HH * CC * 33];   // [ (h*8+c)*33 + r ], 16.9 KB
    __shared__ float sr2[HH * CC];
    __shared__ float sb2[CC];
    for (int i = threadIdx.x; i < RR * HH * CC; i += 256) {
        int r  = i >> 7;       // i / 128
        int hc = i & 127;      // h*8+c
        sw[hc * 33 + r] = w2[i];
    }
    if (threadIdx.x < HH * CC) sr2[threadIdx.x] = root2[threadIdx.x];
    if (threadIdx.x < CC) sb2[threadIdx.x] = b2[threadIdx.x];
    __syncthreads();

    int tid = blockIdx.x * 256 + threadIdx.x;
    int n = tid >> 3;
    int c = tid & 7;
    bool valid = (n < NN);
    if (!valid) n = NN - 1;              // keep warp whole for shfl

    int start = (n > 0) ? __ldg(&g_off[n - 1]) : 0;
    int m     = __ldg(&g_deg[n]);
    float acc = 0.f;
    for (int k = 0; k < m; k++) {
        int2 ep = __ldg(&g_ep[start + k]);
        int src = ep.x & 0xFFFF;
        int r   = ep.x >> 16;
        float inv = __int_as_float(ep.y);
        const float4* xp = (const float4*)(g_x + src * HH);
        float dot = 0.f;
        #pragma unroll
        for (int i4 = 0; i4 < 4; i4++) {
            float4 xv = __ldg(&xp[i4]);   // 8 lanes overlap -> shared sectors
            dot += xv.x * sw[((i4 * 4 + 0) * CC + c) * 33 + r];
            dot += xv.y * sw[((i4 * 4 + 1) * CC + c) * 33 + r];
            dot += xv.z * sw[((i4 * 4 + 2) * CC + c) * 33 + r];
            dot += xv.w * sw[((i4 * 4 + 3) * CC + c) * 33 + r];
        }
        acc += dot * inv;
    }

    // + x[n] @ root2 + b2
    const float4* xp = (const float4*)(g_x + n * HH);
    float o = acc + sb2[c];
    #pragma unroll
    for (int i4 = 0; i4 < 4; i4++) {
        float4 xv = __ldg(&xp[i4]);
        o += xv.x * sr2[(i4 * 4 + 0) * CC + c];
        o += xv.y * sr2[(i4 * 4 + 1) * CC + c];
        o += xv.z * sr2[(i4 * 4 + 2) * CC + c];
        o += xv.w * sr2[(i4 * 4 + 3) * CC + c];
    }

    // log_softmax across the 8-lane class group
    float mx = o;
    #pragma unroll
    for (int d = 1; d < 8; d <<= 1)
        mx = fmaxf(mx, __shfl_xor_sync(0xFFFFFFFF, mx, d));
    float s = expf(o - mx);
    #pragma unroll
    for (int d = 1; d < 8; d <<= 1)
        s += __shfl_xor_sync(0xFFFFFFFF, s, d);
    if (valid) out[n * CC + c] = o - mx - logf(s);
}

// ---------------------------------------------------------------- launch
extern "C" void kernel_launch(void* const* d_in, const int* in_sizes, int n_in,
                              void* d_out, int out_size) {
    const int*   ei    = (const int*)  d_in[0];  // [2, E]
    const int*   et    = (const int*)  d_in[1];  // [E]
    const float* w1    = (const float*)d_in[2];  // [R, N, H]
    const float* root1 = (const float*)d_in[3];  // [N, H]
    const float* b1    = (const float*)d_in[4];  // [H]
    const float* w2    = (const float*)d_in[5];  // [R, H, C]
    const float* root2 = (const float*)d_in[6];  // [H, C]
    const float* b2    = (const float*)d_in[7];  // [C]
    float* out = (float*)d_out;                  // [N, C]

    k_zero   <<<(NN * RR / 4 + 255) / 256, 256>>>();
    k_count  <<<(EE + 255) / 256, 256>>>(ei, et);
    k_scanA  <<<(NN + 255) / 256, 256>>>();
    k_scanB  <<<1, 1024>>>();
    k_scatter<<<(EE + 255) / 256, 256>>>(ei, et);
    k_layer1 <<<(NN * 16 + 255) / 256, 256>>>(w1, root1, b1);
    k_layer2 <<<(NN * 8 + 255) / 256, 256>>>(w2, root2, b2, out);
}

// round 10
// speedup vs baseline: 1.2466x; 1.2466x over previous
#include <cuda_runtime.h>
#include <math.h>

// Problem constants (fixed-shape benchmark)
#define NN 50000
#define HH 16
#define RR 32
#define CC 8
#define EE 1600000

// Scratch (device globals; no allocation allowed)
__device__ float g_cnt[NN * RR];       // per-(dst,rel) counts, [dst][r], 6.4 MB
__device__ int   g_deg[NN];            // per-dst degree
__device__ int   g_off[NN];            // segment cursor; post-scatter = start+deg
__device__ int   g_total;              // global segment allocator
__device__ int2  g_ep[EE];             // per-edge record: (src | r<<16, bitcast 1/cnt)
__device__ float g_x[NN * HH];         // layer-1 node features, 3.2 MB
__device__ float g_xw[RR * NN * CC];   // per-relation transformed feats, 51.2 MB

// ---------------------------------------------------------------- (0) zero cnt + total
__global__ void k_zero() {
    int i = blockIdx.x * blockDim.x + threadIdx.x;
    if (i < NN * RR / 4) ((float4*)g_cnt)[i] = make_float4(0.f, 0.f, 0.f, 0.f);
    if (i == 0) g_total = 0;
}

// ---------------------------------------------------------------- (1) count per (dst, rel)
__global__ void k_count(const int* __restrict__ ei, const int* __restrict__ et) {
    int e = blockIdx.x * blockDim.x + threadIdx.x;
    if (e >= EE) return;
    int dst = __ldg(ei + EE + e);
    int r   = __ldg(et + e);
    atomicAdd(&g_cnt[dst * RR + r], 1.0f);
}

// ---------------------------------------------------------------- (2) deg + block-local offsets
// Per-block exclusive scan; block base from one global atomicAdd. Segment
// placement is nondeterministic across blocks but disjoint and valid.
__global__ void __launch_bounds__(256) k_off() {
    __shared__ int s[256];
    __shared__ int sbase;
    int n = blockIdx.x * 256 + threadIdx.x;
    int deg = 0;
    if (n < NN) {
        const float4* p = (const float4*)(g_cnt + n * RR);
        float sum = 0.f;
        #pragma unroll
        for (int i = 0; i < RR / 4; i++) {
            float4 v = __ldg(&p[i]);
            sum += v.x + v.y + v.z + v.w;
        }
        deg = (int)(sum + 0.5f);
    }
    s[threadIdx.x] = deg;
    __syncthreads();
    // inclusive scan over 256
    #pragma unroll
    for (int d = 1; d < 256; d <<= 1) {
        int v = (threadIdx.x >= d) ? s[threadIdx.x - d] : 0;
        __syncthreads();
        s[threadIdx.x] += v;
        __syncthreads();
    }
    if (threadIdx.x == 255) sbase = atomicAdd(&g_total, s[255]);
    __syncthreads();
    if (n < NN) {
        g_deg[n] = deg;
        g_off[n] = sbase + s[threadIdx.x] - deg;   // exclusive
    }
}

// ---------------------------------------------------------------- (3) scatter packed edge records
__global__ void k_scatter(const int* __restrict__ ei, const int* __restrict__ et) {
    int e = blockIdx.x * blockDim.x + threadIdx.x;
    if (e >= EE) return;
    int src = __ldg(ei + e);
    int dst = __ldg(ei + EE + e);
    int r   = __ldg(et + e);
    float inv = __frcp_rn(g_cnt[dst * RR + r]);   // cnt >= 1 for existing edges
    int pos = atomicAdd(&g_off[dst], 1);
    g_ep[pos] = make_int2(src | (r << 16), __float_as_int(inv));
}

// ---------------------------------------------------------------- (4) layer 1, CSR, 16 lanes/node, fused act
__global__ void __launch_bounds__(256)
k_layer1(const float* __restrict__ w1, const float* __restrict__ root1,
         const float* __restrict__ b1) {
    int tid = blockIdx.x * 256 + threadIdx.x;
    int n = tid >> 4;
    int f = tid & 15;
    if (n >= NN) return;
    int m     = __ldg(&g_deg[n]);
    int start = __ldg(&g_off[n]) - m;   // off is post-scatter = start + deg
    float acc = 0.f;
    int k = 0;
    for (; k + 8 <= m; k += 8) {
        int2 e0 = __ldg(&g_ep[start + k]);
        int2 e1 = __ldg(&g_ep[start + k + 1]);
        int2 e2 = __ldg(&g_ep[start + k + 2]);
        int2 e3 = __ldg(&g_ep[start + k + 3]);
        int2 e4 = __ldg(&g_ep[start + k + 4]);
        int2 e5 = __ldg(&g_ep[start + k + 5]);
        int2 e6 = __ldg(&g_ep[start + k + 6]);
        int2 e7 = __ldg(&g_ep[start + k + 7]);
        float w0 = __ldg(&w1[(((e0.x >> 16) * NN + (e0.x & 0xFFFF)) << 4) + f]);
        float w1v= __ldg(&w1[(((e1.x >> 16) * NN + (e1.x & 0xFFFF)) << 4) + f]);
        float w2v= __ldg(&w1[(((e2.x >> 16) * NN + (e2.x & 0xFFFF)) << 4) + f]);
        float w3v= __ldg(&w1[(((e3.x >> 16) * NN + (e3.x & 0xFFFF)) << 4) + f]);
        float w4v= __ldg(&w1[(((e4.x >> 16) * NN + (e4.x & 0xFFFF)) << 4) + f]);
        float w5v= __ldg(&w1[(((e5.x >> 16) * NN + (e5.x & 0xFFFF)) << 4) + f]);
        float w6v= __ldg(&w1[(((e6.x >> 16) * NN + (e6.x & 0xFFFF)) << 4) + f]);
        float w7v= __ldg(&w1[(((e7.x >> 16) * NN + (e7.x & 0xFFFF)) << 4) + f]);
        acc += w0 * __int_as_float(e0.y);
        acc += w1v * __int_as_float(e1.y);
        acc += w2v * __int_as_float(e2.y);
        acc += w3v * __int_as_float(e3.y);
        acc += w4v * __int_as_float(e4.y);
        acc += w5v * __int_as_float(e5.y);
        acc += w6v * __int_as_float(e6.y);
        acc += w7v * __int_as_float(e7.y);
    }
    for (; k < m; k++) {
        int2 ep = __ldg(&g_ep[start + k]);
        float w = __ldg(&w1[(((ep.x >> 16) * NN + (ep.x & 0xFFFF)) << 4) + f]);
        acc += w * __int_as_float(ep.y);
    }
    float v = acc + __ldg(&root1[n * 16 + f]) + __ldg(&b1[f]);
    g_x[n * 16 + f] = fmaxf(v, 0.f);
}

// ---------------------------------------------------------------- (5) xw materialization
// xw[r, n, :] = x[n, :] @ w2[r]
__global__ void __launch_bounds__(256)
k_xw(const float* __restrict__ w2) {
    __shared__ float sw[2 * HH * CC];
    int idx0 = blockIdx.x * 256;
    int r0 = idx0 / NN;
    int r1 = (idx0 + 255) / NN;
    int nrel = r1 - r0 + 1;
    for (int i = threadIdx.x; i < nrel * HH * CC; i += 256)
        sw[i] = w2[r0 * HH * CC + i];
    __syncthreads();

    int idx = idx0 + threadIdx.x;       // over RR*NN
    if (idx >= RR * NN) return;
    int r = idx / NN;
    int n = idx - r * NN;
    const float4* xp = (const float4*)(g_x + n * HH);
    const float* w = sw + (r - r0) * HH * CC;

    float acc[CC];
    #pragma unroll
    for (int c = 0; c < CC; c++) acc[c] = 0.f;

    #pragma unroll
    for (int i4 = 0; i4 < 4; i4++) {
        float4 xv = xp[i4];
        float xs[4] = {xv.x, xv.y, xv.z, xv.w};
        #pragma unroll
        for (int j = 0; j < 4; j++) {
            int h = i4 * 4 + j;
            #pragma unroll
            for (int c = 0; c < CC; c++)
                acc[c] += xs[j] * w[h * CC + c];
        }
    }
    float4* op = (float4*)(g_xw + (size_t)idx * CC);
    op[0] = make_float4(acc[0], acc[1], acc[2], acc[3]);
    op[1] = make_float4(acc[4], acc[5], acc[6], acc[7]);
}

// ---------------------------------------------------------------- (6) layer 2, CSR, 8 lanes/node, xw gather, fused epilogue
__global__ void __launch_bounds__(256)
k_layer2(const float* __restrict__ root2, const float* __restrict__ b2,
         float* __restrict__ out) {
    __shared__ float sr2[HH * CC];
    __shared__ float sb2[CC];
    if (threadIdx.x < HH * CC) sr2[threadIdx.x] = root2[threadIdx.x];
    if (threadIdx.x < CC) sb2[threadIdx.x] = b2[threadIdx.x];
    __syncthreads();

    int tid = blockIdx.x * 256 + threadIdx.x;
    int n = tid >> 3;
    int c = tid & 7;
    bool valid = (n < NN);
    if (!valid) n = NN - 1;              // keep warp whole for shfl

    int m     = __ldg(&g_deg[n]);
    int start = __ldg(&g_off[n]) - m;
    float acc = 0.f;
    int k = 0;
    for (; k + 4 <= m; k += 4) {
        int2 e0 = __ldg(&g_ep[start + k]);
        int2 e1 = __ldg(&g_ep[start + k + 1]);
        int2 e2 = __ldg(&g_ep[start + k + 2]);
        int2 e3 = __ldg(&g_ep[start + k + 3]);
        float v0 = __ldg(&g_xw[((size_t)(e0.x >> 16) * NN + (e0.x & 0xFFFF)) * CC + c]);
        float v1 = __ldg(&g_xw[((size_t)(e1.x >> 16) * NN + (e1.x & 0xFFFF)) * CC + c]);
        float v2 = __ldg(&g_xw[((size_t)(e2.x >> 16) * NN + (e2.x & 0xFFFF)) * CC + c]);
        float v3 = __ldg(&g_xw[((size_t)(e3.x >> 16) * NN + (e3.x & 0xFFFF)) * CC + c]);
        acc += v0 * __int_as_float(e0.y);
        acc += v1 * __int_as_float(e1.y);
        acc += v2 * __int_as_float(e2.y);
        acc += v3 * __int_as_float(e3.y);
    }
    for (; k < m; k++) {
        int2 ep = __ldg(&g_ep[start + k]);
        float v = __ldg(&g_xw[((size_t)(ep.x >> 16) * NN + (ep.x & 0xFFFF)) * CC + c]);
        acc += v * __int_as_float(ep.y);
    }

    // + x[n] @ root2 + b2
    const float4* xp = (const float4*)(g_x + n * HH);
    float o = acc + sb2[c];
    #pragma unroll
    for (int i4 = 0; i4 < 4; i4++) {
        float4 xv = __ldg(&xp[i4]);
        o += xv.x * sr2[(i4 * 4 + 0) * CC + c];
        o += xv.y * sr2[(i4 * 4 + 1) * CC + c];
        o += xv.z * sr2[(i4 * 4 + 2) * CC + c];
        o += xv.w * sr2[(i4 * 4 + 3) * CC + c];
    }

    // log_softmax across the 8-lane class group
    float mx = o;
    #pragma unroll
    for (int d = 1; d < 8; d <<= 1)
        mx = fmaxf(mx, __shfl_xor_sync(0xFFFFFFFF, mx, d));
    float s = expf(o - mx);
    #pragma unroll
    for (int d = 1; d < 8; d <<= 1)
        s += __shfl_xor_sync(0xFFFFFFFF, s, d);
    if (valid) out[n * CC + c] = o - mx - logf(s);
}

// ---------------------------------------------------------------- launch
extern "C" void kernel_launch(void* const* d_in, const int* in_sizes, int n_in,
                              void* d_out, int out_size) {
    const int*   ei    = (const int*)  d_in[0];  // [2, E]
    const int*   et    = (const int*)  d_in[1];  // [E]
    const float* w1    = (const float*)d_in[2];  // [R, N, H]
    const float* root1 = (const float*)d_in[3];  // [N, H]
    const float* b1    = (const float*)d_in[4];  // [H]
    const float* w2    = (const float*)d_in[5];  // [R, H, C]
    const float* root2 = (const float*)d_in[6];  // [H, C]
    const float* b2    = (const float*)d_in[7];  // [C]
    float* out = (float*)d_out;                  // [N, C]

    k_zero   <<<(NN * RR / 4 + 255) / 256, 256>>>();
    k_count  <<<(EE + 255) / 256, 256>>>(ei, et);
    k_off    <<<(NN + 255) / 256, 256>>>();
    k_scatter<<<(EE + 255) / 256, 256>>>(ei, et);   // launch idx 3 -> profiled
    k_layer1 <<<(NN * 16 + 255) / 256, 256>>>(w1, root1, b1);
    k_xw     <<<(RR * NN + 255) / 256, 256>>>(w2);
    k_layer2 <<<(NN * 8 + 255) / 256, 256>>>(root2, b2, out);
}